// round 13
// baseline (speedup 1.0000x reference)
#include <cuda_runtime.h>

#define BB 32
#define CC 256
#define NN 1024          // H*W
#define MM 48            // grid nodes
#define SEGS 45          // usable intervals = MM-3
#define TCW 128          // c-tile width in k2
#define KSPLIT 4
#define KSL (NN/KSPLIT)  // 256 j per block
#define KCH 32           // j chunk

// ---------------- scratch (device globals; no allocation) ----------------
__device__ float g_a[BB*NN];
__device__ float g_k[BB*NN];
__device__ unsigned g_mm[BB*2];                  // encoded min/max of a per batch
__device__ __align__(16) float g_S[BB*MM*CC];    // table S[b][m][c]
__device__ float g_Z[BB*MM];                     // table Z[b][m]

// order-preserving float<->uint encoding for atomicMin/Max
static __device__ __forceinline__ unsigned enc_f(float f){
    unsigned b = __float_as_uint(f);
    return (b & 0x80000000u) ? ~b : (b | 0x80000000u);
}
static __device__ __forceinline__ float dec_f(unsigned e){
    unsigned b = (e & 0x80000000u) ? (e ^ 0x80000000u) : ~e;
    return __uint_as_float(b);
}
// identical expression in k2 and k3 -> identical IEEE results
static __device__ __forceinline__ void get_grid(int b, float& lo, float& hs){
    float amin = dec_f(g_mm[2*b]);
    float amax = dec_f(g_mm[2*b+1]);
    lo = amin - 1e-4f;
    float hi = amax + 1e-4f;
    hs = (hi - lo) * (1.0f/(float)SEGS);
}

// ---------------- k0: zero tables, init min/max ----------------
__global__ void k_init(){
    int idx = blockIdx.x*blockDim.x + threadIdx.x;
    int n4 = (BB*MM*CC)/4;
    if (idx < n4) reinterpret_cast<float4*>(g_S)[idx] = make_float4(0.f,0.f,0.f,0.f);
    if (idx < BB*MM) g_Z[idx] = 0.f;
    if (idx < BB){ g_mm[2*idx] = 0xFFFFFFFFu; g_mm[2*idx+1] = 0u; }
}

// ---------------- k1: a,k scalars + per-batch min/max(a) ----------------
__global__ void __launch_bounds__(256) k1(const float* __restrict__ h,
                                          const float* __restrict__ w1,
                                          const float* __restrict__ b1,
                                          const float* __restrict__ w2,
                                          const float* __restrict__ b2){
    __shared__ float w1s[CC], w2s[CC];
    __shared__ float smn[8], smx[8];
    int b  = blockIdx.x >> 2;
    int pc = blockIdx.x & 3;
    int tid = threadIdx.x;
    w1s[tid] = w1[tid];
    w2s[tid] = w2[tid];
    __syncthreads();

    int p = pc*256 + tid;
    const float* hp = h + (size_t)b*CC*NN + p;
    float av = b1[0], kv = b2[0];
#pragma unroll 8
    for (int c = 0; c < CC; ++c){
        float x = hp[(size_t)c*NN];
        av = fmaf(x, w1s[c], av);
        kv = fmaf(x, w2s[c], kv);
    }
    g_a[b*NN + p] = av;
    g_k[b*NN + p] = kv;

    float mn = av, mx = av;
#pragma unroll
    for (int o = 16; o; o >>= 1){
        mn = fminf(mn, __shfl_xor_sync(0xFFFFFFFFu, mn, o));
        mx = fmaxf(mx, __shfl_xor_sync(0xFFFFFFFFu, mx, o));
    }
    int w = tid >> 5;
    if ((tid & 31) == 0){ smn[w] = mn; smx[w] = mx; }
    __syncthreads();
    if (tid == 0){
#pragma unroll
        for (int i = 1; i < 8; ++i){ mn = fminf(mn, smn[i]); mx = fmaxf(mx, smx[i]); }
        atomicMin(&g_mm[2*b],   enc_f(mn));
        atomicMax(&g_mm[2*b+1], enc_f(mx));
    }
}

// ---------------- k2: table matmul S[b][m][c] += sum_j g(node_m + k_j) * h[b][c][j] ----------------
// grid (32, 2, 4) = (batch, c-tile of 128, K-split of 256) ; 128 threads
__global__ void __launch_bounds__(128) k2(const float* __restrict__ h){
    __shared__ __align__(16) float Gs[KCH*50];    // [jj][m], pad 50
    __shared__ __align__(16) float Xs[KCH*129];   // [jj][cc], pad 129

    int b  = blockIdx.x;
    int ct = blockIdx.y;
    int ks = blockIdx.z;
    int tid = threadIdx.x;

    float lo, hs; get_grid(b, lo, hs);
    float rmul = __expf(2.0f*hs);

    int c0  = ct*TCW;
    int j0b = ks*KSL;

    int jj_e = tid >> 2;          // 0..31 for G eval
    int mq   = tid & 3;           // 12 nodes each
    int tm   = tid >> 4;          // 0..7
    int tc   = tid & 15;          // 0..15
    int m0   = tm*6;

    unsigned long long acc[3][8];
#pragma unroll
    for (int i = 0; i < 3; ++i)
#pragma unroll
        for (int q = 0; q < 8; ++q) acc[i][q] = 0ull;

    bool doz = (ct == 0) && (tid < MM);
    float zacc = 0.f;

    for (int ch = 0; ch < KSL/KCH; ++ch){
        int j0 = j0b + ch*KCH;

        // --- G eval: exp(tanh(node_m + k_j)) via e^{2s} recurrence ---
        {
            float kv = __ldg(&g_k[b*NN + j0 + jj_e]);
            float s0 = lo + (float)(mq*12 - 1)*hs + kv;
            float t  = __expf(2.0f*s0);
#pragma unroll
            for (int i = 0; i < 12; ++i){
                float u = __fdividef(t - 1.0f, t + 1.0f); // tanh
                Gs[jj_e*50 + mq*12 + i] = __expf(u);
                t *= rmul;
            }
        }
        // --- X stage: h[b][c0+cc][j0..j0+31] -> Xs[jj][cc] (conflict-free) ---
#pragma unroll
        for (int it = 0; it < 8; ++it){
            int idx = it*128 + tid;
            int cc = idx >> 3, q4 = idx & 7;
            float4 v = *reinterpret_cast<const float4*>(
                &h[((size_t)b*CC + (c0+cc))*NN + j0 + q4*4]);
            Gs[0] = Gs[0]; // no-op
            Xs[(q4*4+0)*129 + cc] = v.x;
            Xs[(q4*4+1)*129 + cc] = v.y;
            Xs[(q4*4+2)*129 + cc] = v.z;
            Xs[(q4*4+3)*129 + cc] = v.w;
        }
        __syncthreads();

        if (doz){
            float zs = 0.f;
#pragma unroll
            for (int jj = 0; jj < KCH; ++jj) zs += Gs[jj*50 + tid];
            zacc += zs;
        }

        // --- inner product: FFMA2, m-pairs packed ---
#pragma unroll 8
        for (int jj = 0; jj < KCH; ++jj){
            unsigned long long gA = *reinterpret_cast<const unsigned long long*>(&Gs[jj*50 + m0 + 0]);
            unsigned long long gB = *reinterpret_cast<const unsigned long long*>(&Gs[jj*50 + m0 + 2]);
            unsigned long long gC = *reinterpret_cast<const unsigned long long*>(&Gs[jj*50 + m0 + 4]);
#pragma unroll
            for (int q = 0; q < 8; ++q){
                float x = Xs[jj*129 + tc + 16*q];
                unsigned long long xx;
                asm("mov.b64 %0, {%1,%1};" : "=l"(xx) : "f"(x));
                asm("fma.rn.f32x2 %0, %1, %2, %0;" : "+l"(acc[0][q]) : "l"(gA), "l"(xx));
                asm("fma.rn.f32x2 %0, %1, %2, %0;" : "+l"(acc[1][q]) : "l"(gB), "l"(xx));
                asm("fma.rn.f32x2 %0, %1, %2, %0;" : "+l"(acc[2][q]) : "l"(gC), "l"(xx));
            }
        }
        __syncthreads();
    }

    // --- writeback ---
#pragma unroll
    for (int i = 0; i < 3; ++i)
#pragma unroll
        for (int q = 0; q < 8; ++q){
            float vlo, vhi;
            asm("mov.b64 {%0,%1}, %2;" : "=f"(vlo), "=f"(vhi) : "l"(acc[i][q]));
            int m = m0 + 2*i;
            int c = c0 + tc + 16*q;
            atomicAdd(&g_S[((size_t)b*MM + m  )*CC + c], vlo);
            atomicAdd(&g_S[((size_t)b*MM + m+1)*CC + c], vhi);
        }
    if (doz) atomicAdd(&g_Z[b*MM + tid], zacc);
}

// ---------------- k3: cubic-Lagrange interpolate + LeakyReLU + write ----------------
__global__ void __launch_bounds__(256) k3(float* __restrict__ out){
    int b  = blockIdx.x >> 2;
    int pc = blockIdx.x & 3;
    int tid = threadIdx.x;
    int p = pc*256 + tid;

    float lo, hs; get_grid(b, lo, hs);
    float a = g_a[b*NN + p];
    float u = (a - lo) / hs;
    int seg = (int)floorf(u);
    seg = max(0, min(SEGS-1, seg));
    float s = u - (float)seg;

    // Lagrange weights for nodes at offsets {-1,0,1,2}, s in [0,1]
    float w0 = -s*(s-1.f)*(s-2.f)*(1.f/6.f);
    float w1 = (s*s-1.f)*(s-2.f)*0.5f;
    float w2 = -s*(s+1.f)*(s-2.f)*0.5f;
    float w3 = s*(s*s-1.f)*(1.f/6.f);

    const float* Zb = &g_Z[b*MM + seg];
    float z  = w0*Zb[0] + w1*Zb[1] + w2*Zb[2] + w3*Zb[3];
    float rz = 1.0f / z;

    const float4* S0 = reinterpret_cast<const float4*>(&g_S[((size_t)b*MM + seg)*CC]);
    float* op = out + (size_t)b*CC*NN + p;

#pragma unroll 4
    for (int c4 = 0; c4 < CC/4; ++c4){
        float4 r0 = __ldg(&S0[c4]);
        float4 r1 = __ldg(&S0[c4 + 64]);
        float4 r2 = __ldg(&S0[c4 + 128]);
        float4 r3 = __ldg(&S0[c4 + 192]);
        float v0 = (w0*r0.x + w1*r1.x + w2*r2.x + w3*r3.x)*rz;
        float v1 = (w0*r0.y + w1*r1.y + w2*r2.y + w3*r3.y)*rz;
        float v2 = (w0*r0.z + w1*r1.z + w2*r2.z + w3*r3.z)*rz;
        float v3 = (w0*r0.w + w1*r1.w + w2*r2.w + w3*r3.w)*rz;
        v0 = (v0 >= 0.f) ? v0 : 0.2f*v0;
        v1 = (v1 >= 0.f) ? v1 : 0.2f*v1;
        v2 = (v2 >= 0.f) ? v2 : 0.2f*v2;
        v3 = (v3 >= 0.f) ? v3 : 0.2f*v3;
        op[(size_t)(c4*4+0)*NN] = v0;
        op[(size_t)(c4*4+1)*NN] = v1;
        op[(size_t)(c4*4+2)*NN] = v2;
        op[(size_t)(c4*4+3)*NN] = v3;
    }
}

// ---------------- entry ----------------
extern "C" void kernel_launch(void* const* d_in, const int* in_sizes, int n_in,
                              void* d_out, int out_size){
    (void)in_sizes; (void)n_in; (void)out_size;
    const float* h  = (const float*)d_in[0];
    const float* w1 = (const float*)d_in[1];
    const float* b1 = (const float*)d_in[2];
    const float* w2 = (const float*)d_in[3];
    const float* b2 = (const float*)d_in[4];
    float* out = (float*)d_out;

    k_init<<<384, 256>>>();
    k1<<<128, 256>>>(h, w1, b1, w2, b2);
    k2<<<dim3(32, 2, 4), 128>>>(h);
    k3<<<128, 256>>>(out);
}

// round 14
// speedup vs baseline: 1.5906x; 1.5906x over previous
#include <cuda_runtime.h>

#define BB 32
#define CC 256
#define NN 1024          // H*W
#define MM 32            // grid nodes
#define SEGS 29          // usable intervals = MM-3
#define TCW 128          // c-tile width in k2
#define KSPLIT 8
#define KSL (NN/KSPLIT)  // 128 j per block
#define KCH 32           // j chunk

// ---------------- scratch (device globals; no allocation) ----------------
__device__ float g_a[BB*NN];
__device__ float g_k[BB*NN];
__device__ unsigned g_mm[BB*2];                  // encoded min/max of a per batch
__device__ __align__(16) float g_S[BB*MM*CC];    // table S[b][m][c]
__device__ float g_Z[BB*MM];                     // table Z[b][m]

// order-preserving float<->uint encoding for atomicMin/Max
static __device__ __forceinline__ unsigned enc_f(float f){
    unsigned b = __float_as_uint(f);
    return (b & 0x80000000u) ? ~b : (b | 0x80000000u);
}
static __device__ __forceinline__ float dec_f(unsigned e){
    unsigned b = (e & 0x80000000u) ? (e ^ 0x80000000u) : ~e;
    return __uint_as_float(b);
}
// identical expression in k2 and k3 -> identical IEEE results
static __device__ __forceinline__ void get_grid(int b, float& lo, float& hs){
    float amin = dec_f(g_mm[2*b]);
    float amax = dec_f(g_mm[2*b+1]);
    lo = amin - 1e-4f;
    float hi = amax + 1e-4f;
    hs = (hi - lo) * (1.0f/(float)SEGS);
}

// ---------------- k0: init min/max + zero Z (1 small block) ----------------
__global__ void k_init(){
    int tid = threadIdx.x;
    if (tid < BB*MM) g_Z[tid] = 0.f;
    if (tid < BB){ g_mm[2*tid] = 0xFFFFFFFFu; g_mm[2*tid+1] = 0u; }
}

// ---------------- k1: a,k scalars + per-batch min/max(a) + zero g_S ----------------
__global__ void __launch_bounds__(256) k1(const float* __restrict__ h,
                                          const float* __restrict__ w1,
                                          const float* __restrict__ b1,
                                          const float* __restrict__ w2,
                                          const float* __restrict__ b2){
    __shared__ float w1s[CC], w2s[CC];
    __shared__ float smn[8], smx[8];
    int b  = blockIdx.x >> 2;
    int pc = blockIdx.x & 3;
    int tid = threadIdx.x;
    w1s[tid] = w1[tid];
    w2s[tid] = w2[tid];

    // zero the S table (32768 threads * 2 float4 = 65536 float4 = g_S)
    {
        int base = (blockIdx.x*256 + tid)*2;
        float4 z4 = make_float4(0.f,0.f,0.f,0.f);
        reinterpret_cast<float4*>(g_S)[base]   = z4;
        reinterpret_cast<float4*>(g_S)[base+1] = z4;
    }
    __syncthreads();

    int p = pc*256 + tid;
    const float* hp = h + (size_t)b*CC*NN + p;
    float av = b1[0], kv = b2[0];
#pragma unroll 8
    for (int c = 0; c < CC; ++c){
        float x = hp[(size_t)c*NN];
        av = fmaf(x, w1s[c], av);
        kv = fmaf(x, w2s[c], kv);
    }
    g_a[b*NN + p] = av;
    g_k[b*NN + p] = kv;

    float mn = av, mx = av;
#pragma unroll
    for (int o = 16; o; o >>= 1){
        mn = fminf(mn, __shfl_xor_sync(0xFFFFFFFFu, mn, o));
        mx = fmaxf(mx, __shfl_xor_sync(0xFFFFFFFFu, mx, o));
    }
    int w = tid >> 5;
    if ((tid & 31) == 0){ smn[w] = mn; smx[w] = mx; }
    __syncthreads();
    if (tid == 0){
#pragma unroll
        for (int i = 1; i < 8; ++i){ mn = fminf(mn, smn[i]); mx = fmaxf(mx, smx[i]); }
        atomicMin(&g_mm[2*b],   enc_f(mn));
        atomicMax(&g_mm[2*b+1], enc_f(mx));
    }
}

// ---------------- k2: S[b][m][c] += sum_j exp(tanh(node_m + k_j)) * h[b][c][j] ----------------
// grid (32, 2, 8) = (batch, c-tile of 128, K-split of 128 j); 128 threads
__global__ void __launch_bounds__(128) k2(const float* __restrict__ h){
    __shared__ __align__(16) float Gs[KCH*66];    // [jj][2m] duplicated g pairs, pad->66
    __shared__ __align__(16) float Xs[KCH*130];   // [jj][cc], pad->130

    int b  = blockIdx.x;
    int ct = blockIdx.y;
    int ks = blockIdx.z;
    int tid = threadIdx.x;

    float lo, hs; get_grid(b, lo, hs);
    float rmul = __expf(2.0f*hs);

    int c0  = ct*TCW;
    int j0b = ks*KSL;

    int jj_e = tid >> 2;          // 0..31 for G eval
    int mq   = tid & 3;           // 8 nodes each
    int tm   = tid >> 4;          // 0..7
    int tc   = tid & 15;          // 0..15
    int m0   = tm*4;              // 4 m-rows per thread

    unsigned long long acc[4][4];
#pragma unroll
    for (int mi = 0; mi < 4; ++mi)
#pragma unroll
        for (int q = 0; q < 4; ++q) acc[mi][q] = 0ull;

    bool doz = (ct == 0) && (tid < MM);
    float zacc = 0.f;

    for (int ch = 0; ch < KSL/KCH; ++ch){
        int j0 = j0b + ch*KCH;

        // --- G eval: exp(tanh(node_m + k_j)) via e^{2s} recurrence, duplicated {g,g} ---
        {
            float kv = __ldg(&g_k[b*NN + j0 + jj_e]);
            float s0 = lo + (float)(mq*8 - 1)*hs + kv;
            float t  = __expf(2.0f*s0);
#pragma unroll
            for (int i = 0; i < 8; ++i){
                float u = __fdividef(t - 1.0f, t + 1.0f); // tanh
                float g = __expf(u);
                *reinterpret_cast<float2*>(&Gs[jj_e*66 + 2*(mq*8+i)]) = make_float2(g, g);
                t *= rmul;
            }
        }
        // --- X stage: h[b][c0+cc][j0..j0+31] -> Xs[jj][cc] ---
#pragma unroll
        for (int it = 0; it < 8; ++it){
            int idx = it*128 + tid;
            int cc = idx >> 3, q4 = idx & 7;
            float4 v = *reinterpret_cast<const float4*>(
                &h[((size_t)b*CC + (c0+cc))*NN + j0 + q4*4]);
            Xs[(q4*4+0)*130 + cc] = v.x;
            Xs[(q4*4+1)*130 + cc] = v.y;
            Xs[(q4*4+2)*130 + cc] = v.z;
            Xs[(q4*4+3)*130 + cc] = v.w;
        }
        __syncthreads();

        if (doz){
            float zs = 0.f;
#pragma unroll
            for (int jj = 0; jj < KCH; ++jj) zs += Gs[jj*66 + 2*tid];
            zacc += zs;
        }

        // --- inner product: pure LDS.64 + FFMA2, no movs ---
#pragma unroll 4
        for (int jj = 0; jj < KCH; ++jj){
            unsigned long long gp[4], xp[4];
#pragma unroll
            for (int mi = 0; mi < 4; ++mi)
                gp[mi] = *reinterpret_cast<const unsigned long long*>(&Gs[jj*66 + 2*(m0+mi)]);
#pragma unroll
            for (int q = 0; q < 4; ++q)
                xp[q] = *reinterpret_cast<const unsigned long long*>(&Xs[jj*130 + 2*(tc+16*q)]);
#pragma unroll
            for (int mi = 0; mi < 4; ++mi)
#pragma unroll
                for (int q = 0; q < 4; ++q)
                    asm("fma.rn.f32x2 %0, %1, %2, %0;"
                        : "+l"(acc[mi][q]) : "l"(gp[mi]), "l"(xp[q]));
        }
        __syncthreads();
    }

    // --- writeback (partial sums across KSPLIT) ---
#pragma unroll
    for (int mi = 0; mi < 4; ++mi)
#pragma unroll
        for (int q = 0; q < 4; ++q){
            float vlo, vhi;
            asm("mov.b64 {%0,%1}, %2;" : "=f"(vlo), "=f"(vhi) : "l"(acc[mi][q]));
            int m = m0 + mi;
            int c = c0 + 2*(tc + 16*q);
            atomicAdd(&g_S[((size_t)b*MM + m)*CC + c],     vlo);
            atomicAdd(&g_S[((size_t)b*MM + m)*CC + c + 1], vhi);
        }
    if (doz) atomicAdd(&g_Z[b*MM + tid], zacc);
}

// ---------------- k3: smem table + cubic-Lagrange interpolate + LeakyReLU ----------------
__global__ void __launch_bounds__(256) k3(float* __restrict__ out){
    __shared__ float Ss[MM*257];   // pad 257 -> gather bank = (seg + c) mod 32, conflict-free
    __shared__ float Zs[MM];

    int b  = blockIdx.x >> 2;
    int pc = blockIdx.x & 3;
    int tid = threadIdx.x;

    // load this batch's table into smem (8192 floats)
    const float4* Sg = reinterpret_cast<const float4*>(&g_S[(size_t)b*MM*CC]);
#pragma unroll
    for (int it = 0; it < 8; ++it){
        int idx = it*256 + tid;            // float4 index 0..2047
        float4 v = __ldg(&Sg[idx]);
        int m = idx >> 6, c = (idx & 63)*4;
        Ss[m*257 + c+0] = v.x;
        Ss[m*257 + c+1] = v.y;
        Ss[m*257 + c+2] = v.z;
        Ss[m*257 + c+3] = v.w;
    }
    if (tid < MM) Zs[tid] = g_Z[b*MM + tid];
    __syncthreads();

    int p = pc*256 + tid;
    float lo, hs; get_grid(b, lo, hs);
    float a = g_a[b*NN + p];
    float u = (a - lo) / hs;
    int seg = (int)floorf(u);
    seg = max(0, min(SEGS-1, seg));
    float s = u - (float)seg;

    // Lagrange weights for nodes at offsets {-1,0,1,2}
    float w0 = -s*(s-1.f)*(s-2.f)*(1.f/6.f);
    float w1 = (s*s-1.f)*(s-2.f)*0.5f;
    float w2 = -s*(s+1.f)*(s-2.f)*0.5f;
    float w3 = s*(s*s-1.f)*(1.f/6.f);

    float z  = w0*Zs[seg] + w1*Zs[seg+1] + w2*Zs[seg+2] + w3*Zs[seg+3];
    float rz = 1.0f / z;

    const float* S0 = &Ss[seg*257];
    float* op = out + (size_t)b*CC*NN + p;

#pragma unroll 8
    for (int c = 0; c < CC; ++c){
        float v = w0*S0[c] + w1*S0[c+257] + w2*S0[c+514] + w3*S0[c+771];
        v *= rz;
        v = (v >= 0.f) ? v : 0.2f*v;
        op[(size_t)c*NN] = v;
    }
}

// ---------------- entry ----------------
extern "C" void kernel_launch(void* const* d_in, const int* in_sizes, int n_in,
                              void* d_out, int out_size){
    (void)in_sizes; (void)n_in; (void)out_size;
    const float* h  = (const float*)d_in[0];
    const float* w1 = (const float*)d_in[1];
    const float* b1 = (const float*)d_in[2];
    const float* w2 = (const float*)d_in[3];
    const float* b2 = (const float*)d_in[4];
    float* out = (float*)d_out;

    k_init<<<1, 1024>>>();
    k1<<<128, 256>>>(h, w1, b1, w2, b2);
    k2<<<dim3(32, 2, 8), 128>>>(h);
    k3<<<128, 256>>>(out);
}

// round 15
// speedup vs baseline: 1.6005x; 1.0062x over previous
#include <cuda_runtime.h>

#define BB 32
#define CC 256
#define NN 1024          // H*W
#define MM 32            // grid nodes
#define SEGS 29          // usable intervals = MM-3
#define TCW 128          // c-tile width in k2
#define KSPLIT 8
#define KSL (NN/KSPLIT)  // 128 j per block
#define KCH 32           // j chunk

// ---------------- scratch (device globals; no allocation) ----------------
__device__ float g_a[BB*NN];
__device__ float g_k[BB*NN];
__device__ unsigned g_mm[BB*2];                  // encoded min/max of a per batch
__device__ __align__(16) float g_S[BB*MM*CC];    // table S[b][m][c]
__device__ float g_Z[BB*MM];                     // table Z[b][m]

// order-preserving float<->uint encoding for atomicMin/Max
static __device__ __forceinline__ unsigned enc_f(float f){
    unsigned b = __float_as_uint(f);
    return (b & 0x80000000u) ? ~b : (b | 0x80000000u);
}
static __device__ __forceinline__ float dec_f(unsigned e){
    unsigned b = (e & 0x80000000u) ? (e ^ 0x80000000u) : ~e;
    return __uint_as_float(b);
}
// identical expression in k2 and k3 -> identical IEEE results
static __device__ __forceinline__ void get_grid(int b, float& lo, float& hs){
    float amin = dec_f(g_mm[2*b]);
    float amax = dec_f(g_mm[2*b+1]);
    lo = amin - 1e-4f;
    float hi = amax + 1e-4f;
    hs = (hi - lo) * (1.0f/(float)SEGS);
}

// ---------------- k0: init min/max + zero Z (1 small block) ----------------
__global__ void k_init(){
    int tid = threadIdx.x;
    if (tid < BB*MM) g_Z[tid] = 0.f;
    if (tid < BB){ g_mm[2*tid] = 0xFFFFFFFFu; g_mm[2*tid+1] = 0u; }
}

// ---------------- k1: a,k scalars + per-batch min/max(a) + zero g_S ----------------
__global__ void __launch_bounds__(256) k1(const float* __restrict__ h,
                                          const float* __restrict__ w1,
                                          const float* __restrict__ b1,
                                          const float* __restrict__ w2,
                                          const float* __restrict__ b2){
    __shared__ float w1s[CC], w2s[CC];
    __shared__ float smn[8], smx[8];
    int b  = blockIdx.x >> 2;
    int pc = blockIdx.x & 3;
    int tid = threadIdx.x;
    w1s[tid] = w1[tid];
    w2s[tid] = w2[tid];

    // zero the S table (32768 threads * 2 float4 = 65536 float4 = g_S)
    {
        int base = (blockIdx.x*256 + tid)*2;
        float4 z4 = make_float4(0.f,0.f,0.f,0.f);
        reinterpret_cast<float4*>(g_S)[base]   = z4;
        reinterpret_cast<float4*>(g_S)[base+1] = z4;
    }
    __syncthreads();

    int p = pc*256 + tid;
    const float* hp = h + (size_t)b*CC*NN + p;
    float av = b1[0], kv = b2[0];
#pragma unroll 8
    for (int c = 0; c < CC; ++c){
        float x = hp[(size_t)c*NN];
        av = fmaf(x, w1s[c], av);
        kv = fmaf(x, w2s[c], kv);
    }
    g_a[b*NN + p] = av;
    g_k[b*NN + p] = kv;

    float mn = av, mx = av;
#pragma unroll
    for (int o = 16; o; o >>= 1){
        mn = fminf(mn, __shfl_xor_sync(0xFFFFFFFFu, mn, o));
        mx = fmaxf(mx, __shfl_xor_sync(0xFFFFFFFFu, mx, o));
    }
    int w = tid >> 5;
    if ((tid & 31) == 0){ smn[w] = mn; smx[w] = mx; }
    __syncthreads();
    if (tid == 0){
#pragma unroll
        for (int i = 1; i < 8; ++i){ mn = fminf(mn, smn[i]); mx = fmaxf(mx, smx[i]); }
        atomicMin(&g_mm[2*b],   enc_f(mn));
        atomicMax(&g_mm[2*b+1], enc_f(mx));
    }
}

// ---------------- k2: S[b][m][c] += sum_j exp(tanh(node_m + k_j)) * h[b][c][j] ----------------
// grid (32, 2, 8) = (batch, c-tile of 128, K-split of 128 j); 128 threads
__global__ void __launch_bounds__(128) k2(const float* __restrict__ h){
    __shared__ __align__(16) float Gs[KCH*66];    // [jj][2m] duplicated g pairs, pad->66
    __shared__ __align__(16) float Xs[KCH*130];   // [jj][cc], pad->130

    int b  = blockIdx.x;
    int ct = blockIdx.y;
    int ks = blockIdx.z;
    int tid = threadIdx.x;

    float lo, hs; get_grid(b, lo, hs);
    float rmul = __expf(2.0f*hs);

    int c0  = ct*TCW;
    int j0b = ks*KSL;

    int jj_e = tid >> 2;          // 0..31 for G eval
    int mq   = tid & 3;           // 8 nodes each
    int tm   = tid >> 4;          // 0..7
    int tc   = tid & 15;          // 0..15
    int m0   = tm*4;              // 4 m-rows per thread

    unsigned long long acc[4][4];
#pragma unroll
    for (int mi = 0; mi < 4; ++mi)
#pragma unroll
        for (int q = 0; q < 4; ++q) acc[mi][q] = 0ull;

    bool doz = (ct == 0) && (tid < MM);
    float zacc = 0.f;

    for (int ch = 0; ch < KSL/KCH; ++ch){
        int j0 = j0b + ch*KCH;

        // --- G eval: exp(tanh(node_m + k_j)) via e^{2s} recurrence, duplicated {g,g} ---
        {
            float kv = __ldg(&g_k[b*NN + j0 + jj_e]);
            float s0 = lo + (float)(mq*8 - 1)*hs + kv;
            float t  = __expf(2.0f*s0);
#pragma unroll
            for (int i = 0; i < 8; ++i){
                float u = __fdividef(t - 1.0f, t + 1.0f); // tanh
                float g = __expf(u);
                *reinterpret_cast<float2*>(&Gs[jj_e*66 + 2*(mq*8+i)]) = make_float2(g, g);
                t *= rmul;
            }
        }
        // --- X stage: h[b][c0+cc][j0..j0+31] -> Xs[jj][cc] ---
#pragma unroll
        for (int it = 0; it < 8; ++it){
            int idx = it*128 + tid;
            int cc = idx >> 3, q4 = idx & 7;
            float4 v = *reinterpret_cast<const float4*>(
                &h[((size_t)b*CC + (c0+cc))*NN + j0 + q4*4]);
            Xs[(q4*4+0)*130 + cc] = v.x;
            Xs[(q4*4+1)*130 + cc] = v.y;
            Xs[(q4*4+2)*130 + cc] = v.z;
            Xs[(q4*4+3)*130 + cc] = v.w;
        }
        __syncthreads();

        if (doz){
            float zs = 0.f;
#pragma unroll
            for (int jj = 0; jj < KCH; ++jj) zs += Gs[jj*66 + 2*tid];
            zacc += zs;
        }

        // --- inner product: pure LDS.64 + FFMA2, no movs ---
#pragma unroll 4
        for (int jj = 0; jj < KCH; ++jj){
            unsigned long long gp[4], xp[4];
#pragma unroll
            for (int mi = 0; mi < 4; ++mi)
                gp[mi] = *reinterpret_cast<const unsigned long long*>(&Gs[jj*66 + 2*(m0+mi)]);
#pragma unroll
            for (int q = 0; q < 4; ++q)
                xp[q] = *reinterpret_cast<const unsigned long long*>(&Xs[jj*130 + 2*(tc+16*q)]);
#pragma unroll
            for (int mi = 0; mi < 4; ++mi)
#pragma unroll
                for (int q = 0; q < 4; ++q)
                    asm("fma.rn.f32x2 %0, %1, %2, %0;"
                        : "+l"(acc[mi][q]) : "l"(gp[mi]), "l"(xp[q]));
        }
        __syncthreads();
    }

    // --- writeback (partial sums across KSPLIT) ---
#pragma unroll
    for (int mi = 0; mi < 4; ++mi)
#pragma unroll
        for (int q = 0; q < 4; ++q){
            float vlo, vhi;
            asm("mov.b64 {%0,%1}, %2;" : "=f"(vlo), "=f"(vhi) : "l"(acc[mi][q]));
            int m = m0 + mi;
            int c = c0 + 2*(tc + 16*q);
            atomicAdd(&g_S[((size_t)b*MM + m)*CC + c],     vlo);
            atomicAdd(&g_S[((size_t)b*MM + m)*CC + c + 1], vhi);
        }
    if (doz) atomicAdd(&g_Z[b*MM + tid], zacc);
}

// ---------------- k3: smem table + cubic-Lagrange interpolate + LeakyReLU ----------------
__global__ void __launch_bounds__(256) k3(float* __restrict__ out){
    __shared__ float Ss[MM*257];   // pad 257 -> gather bank = (seg + c) mod 32, conflict-free
    __shared__ float Zs[MM];

    int b  = blockIdx.x >> 2;
    int pc = blockIdx.x & 3;
    int tid = threadIdx.x;

    // load this batch's table into smem (8192 floats)
    const float4* Sg = reinterpret_cast<const float4*>(&g_S[(size_t)b*MM*CC]);
#pragma unroll
    for (int it = 0; it < 8; ++it){
        int idx = it*256 + tid;            // float4 index 0..2047
        float4 v = __ldg(&Sg[idx]);
        int m = idx >> 6, c = (idx & 63)*4;
        Ss[m*257 + c+0] = v.x;
        Ss[m*257 + c+1] = v.y;
        Ss[m*257 + c+2] = v.z;
        Ss[m*257 + c+3] = v.w;
    }
    if (tid < MM) Zs[tid] = g_Z[b*MM + tid];
    __syncthreads();

    int p = pc*256 + tid;
    float lo, hs; get_grid(b, lo, hs);
    float a = g_a[b*NN + p];
    float u = (a - lo) / hs;
    int seg = (int)floorf(u);
    seg = max(0, min(SEGS-1, seg));
    float s = u - (float)seg;

    // Lagrange weights for nodes at offsets {-1,0,1,2}
    float w0 = -s*(s-1.f)*(s-2.f)*(1.f/6.f);
    float w1 = (s*s-1.f)*(s-2.f)*0.5f;
    float w2 = -s*(s+1.f)*(s-2.f)*0.5f;
    float w3 = s*(s*s-1.f)*(1.f/6.f);

    float z  = w0*Zs[seg] + w1*Zs[seg+1] + w2*Zs[seg+2] + w3*Zs[seg+3];
    float rz = 1.0f / z;

    const float* S0 = &Ss[seg*257];
    float* op = out + (size_t)b*CC*NN + p;

#pragma unroll 8
    for (int c = 0; c < CC; ++c){
        float v = w0*S0[c] + w1*S0[c+257] + w2*S0[c+514] + w3*S0[c+771];
        v *= rz;
        v = (v >= 0.f) ? v : 0.2f*v;
        op[(size_t)c*NN] = v;
    }
}

// ---------------- entry ----------------
extern "C" void kernel_launch(void* const* d_in, const int* in_sizes, int n_in,
                              void* d_out, int out_size){
    (void)in_sizes; (void)n_in; (void)out_size;
    const float* h  = (const float*)d_in[0];
    const float* w1 = (const float*)d_in[1];
    const float* b1 = (const float*)d_in[2];
    const float* w2 = (const float*)d_in[3];
    const float* b2 = (const float*)d_in[4];
    float* out = (float*)d_out;

    k_init<<<1, 1024>>>();
    k1<<<128, 256>>>(h, w1, b1, w2, b2);
    k2<<<dim3(32, 2, 8), 128>>>(h);
    k3<<<128, 256>>>(out);
}